// round 14
// baseline (speedup 1.0000x reference)
#include <cuda_runtime.h>
#include <cuda_bf16.h>
#include <cstdint>

#define N_NODES 16384
#define D       128
#define R_T     5
#define H_H     4
#define E_EDGES 262144
#define MAXDEG  128   // Poisson(16) tail: P(deg>=128) ~ 1e-60

typedef unsigned long long u64;

// ---------------- device scratch (static globals; no allocation) ----------------
__device__ float g_K[R_T * N_NODES * D];      // 41.9 MB
__device__ float g_Q[R_T * N_NODES * D];      // 41.9 MB
__device__ float g_V[R_T * N_NODES * D];      // 41.9 MB
__device__ float g_agg[N_NODES * 512];        // 33.5MB [N][H*D]
__device__ int   g_cursor[N_NODES];           // zero-init; agg resets each replay
__device__ int   g_e_idx[N_NODES * MAXDEG];   // padded CSR: r*N + src
__device__ float4 g_e_score[N_NODES * MAXDEG];// padded CSR: exp(score) per head

// ---------------- helpers ----------------
__device__ __forceinline__ uint32_t f2tf32(float x) {
    uint32_t r;
    asm("cvt.rna.tf32.f32 %0, %1;" : "=r"(r) : "f"(x));
    return r;
}
__device__ __forceinline__ void mma_tf32(float d[4], const uint32_t a[4],
                                         uint32_t b0, uint32_t b1) {
    asm volatile(
        "mma.sync.aligned.m16n8k8.row.col.f32.tf32.tf32.f32 "
        "{%0,%1,%2,%3}, {%4,%5,%6,%7}, {%8,%9}, {%0,%1,%2,%3};"
        : "+f"(d[0]), "+f"(d[1]), "+f"(d[2]), "+f"(d[3])
        : "r"(a[0]), "r"(a[1]), "r"(a[2]), "r"(a[3]), "r"(b0), "r"(b1));
}

// ---- shared tc-GEMM fragment machinery (swizzles verified R7/R8) ----
// Stage nrows x 128 fp32 (row-major) into swizzled tf32 smem tile.
__device__ __forceinline__ void stage_A_rows(
    float* h_s, const float4* __restrict__ src4, int rowStride4, int rowBase,
    int colq0, int tid, int nrows)
{
    for (int idx = tid; idx < nrows * 32; idx += 512) {
        int n  = idx >> 5;
        int kq = idx & 31;
        float4 v = src4[(size_t)(rowBase + n) * rowStride4 + colq0 + kq];
        uint4 t;
        t.x = f2tf32(v.x); t.y = f2tf32(v.y);
        t.z = f2tf32(v.z); t.w = f2tf32(v.w);
        *(uint4*)(h_s + n * 128 + ((kq * 4) ^ ((n & 7) << 2))) = t;
    }
}

__device__ __forceinline__ void stage_B(
    float* w_s, const float4* __restrict__ W4, int kBase, int tid)
{
    for (int idx = tid; idx < 4096; idx += 512) {
        int k  = idx >> 5;
        int cq = idx & 31;
        float4 v = W4[(size_t)(kBase + k) * 32 + cq];
        uint4 t;
        t.x = f2tf32(v.x); t.y = f2tf32(v.y);
        t.z = f2tf32(v.z); t.w = f2tf32(v.w);
        *(uint4*)(w_s + k * 128 + ((cq * 4) ^ ((k & 3) << 3))) = t;
    }
}

// 16 k8-steps, warp tile 16 nodes x 64 cols (used by final_gemm_tc).
__device__ __forceinline__ void mma_tile(
    const uint32_t* __restrict__ hsu, const uint32_t* __restrict__ wsu,
    int nA, int xrA, int cbase, int gid, int tig, float acc[8][4])
{
    #pragma unroll 4
    for (int ks = 0; ks < 16; ks++) {
        int k0 = ks * 8 + tig;
        int ka  = k0 ^ xrA;
        int ka4 = (k0 + 4) ^ xrA;
        uint32_t a[4];
        a[0] = hsu[(nA    ) * 128 + ka ];
        a[1] = hsu[(nA + 8) * 128 + ka ];
        a[2] = hsu[(nA    ) * 128 + ka4];
        a[3] = hsu[(nA + 8) * 128 + ka4];
        #pragma unroll
        for (int nt = 0; nt < 8; nt++) {
            int cs = (cbase + nt * 8 + gid) ^ (tig << 3);
            uint32_t b0 = wsu[ k0      * 128 + cs];
            uint32_t b1 = wsu[(k0 + 4) * 128 + cs];
            mma_tf32(acc[nt], a, b0, b1);
        }
    }
}

__global__ void dummy_kernel() {}

// Tensor-core QKV: grid (N/256, R), 512 threads, 192 KB dyn smem.
// Block tile 256 nodes x 128 cols; warp tile 32 nodes x 64 cols (2 m16 tiles
// amortize B-fragment LDS: 1.5 LDS/mma vs 2.5 before).
__global__ void __launch_bounds__(512) qkv_gemm_tc(
    const float* __restrict__ h,
    const float* __restrict__ Wk, const float* __restrict__ bk,
    const float* __restrict__ Wq, const float* __restrict__ bq,
    const float* __restrict__ Wv, const float* __restrict__ bv)
{
    extern __shared__ float smem[];
    float* h_s = smem;            // 256 x 128 tf32 (128 KB)
    float* w_s = smem + 32768;    // 128 x 128 tf32 (64 KB)

    int r = blockIdx.y;
    int nodeBase = blockIdx.x * 256;
    int tid = threadIdx.x;

    stage_A_rows(h_s, (const float4*)h, 32, nodeBase, 0, tid, 256);

    int lane = tid & 31, wid = tid >> 5;
    int gid = lane >> 2, tig = lane & 3;
    int wrow = wid & 7, wcol = wid >> 3;
    int cbase = wcol * 64;
    int nA = wrow * 32 + gid;
    int xrA = gid << 2;

    const uint32_t* hsu = (const uint32_t*)h_s;
    const uint32_t* wsu = (const uint32_t*)w_s;

    #pragma unroll 1
    for (int which = 0; which < 3; which++) {
        const float* W; const float* b; float* out;
        if (which == 0)      { W = Wk; b = bk; out = g_K; }
        else if (which == 1) { W = Wq; b = bq; out = g_Q; }
        else                 { W = Wv; b = bv; out = g_V; }
        W += r * D * D;
        b += r * D;
        out += (size_t)r * N_NODES * D;

        __syncthreads();
        stage_B(w_s, (const float4*)W, 0, tid);
        __syncthreads();

        float acc[2][8][4];
        #pragma unroll
        for (int nt = 0; nt < 8; nt++) {
            float2 bv2 = *(const float2*)(b + cbase + nt * 8 + 2 * tig);
            #pragma unroll
            for (int mt = 0; mt < 2; mt++) {
                acc[mt][nt][0] = bv2.x; acc[mt][nt][1] = bv2.y;
                acc[mt][nt][2] = bv2.x; acc[mt][nt][3] = bv2.y;
            }
        }

        #pragma unroll 4
        for (int ks = 0; ks < 16; ks++) {
            int k0 = ks * 8 + tig;
            int ka  = k0 ^ xrA;
            int ka4 = (k0 + 4) ^ xrA;
            uint32_t a0[4], a1[4];
            a0[0] = hsu[(nA     ) * 128 + ka ];
            a0[1] = hsu[(nA +  8) * 128 + ka ];
            a0[2] = hsu[(nA     ) * 128 + ka4];
            a0[3] = hsu[(nA +  8) * 128 + ka4];
            a1[0] = hsu[(nA + 16) * 128 + ka ];
            a1[1] = hsu[(nA + 24) * 128 + ka ];
            a1[2] = hsu[(nA + 16) * 128 + ka4];
            a1[3] = hsu[(nA + 24) * 128 + ka4];
            #pragma unroll
            for (int nt = 0; nt < 8; nt++) {
                int cs = (cbase + nt * 8 + gid) ^ (tig << 3);
                uint32_t b0 = wsu[ k0      * 128 + cs];
                uint32_t b1 = wsu[(k0 + 4) * 128 + cs];
                mma_tf32(acc[0][nt], a0, b0, b1);
                mma_tf32(acc[1][nt], a1, b0, b1);
            }
        }

        #pragma unroll
        for (int mt = 0; mt < 2; mt++) {
            int row0 = nodeBase + wrow * 32 + mt * 16 + gid;
            #pragma unroll
            for (int nt = 0; nt < 8; nt++) {
                int col0 = cbase + nt * 8 + 2 * tig;
                *(float2*)(out + (size_t)row0 * D + col0) =
                    make_float2(acc[mt][nt][0], acc[mt][nt][1]);
                *(float2*)(out + (size_t)(row0 + 8) * D + col0) =
                    make_float2(acc[mt][nt][2], acc[mt][nt][3]);
            }
        }
    }
}

// Per-edge attention scores: 2 edges per warp, MLP-4 gathers, direct CSR write.
__global__ void __launch_bounds__(256) score_kernel(
    const int* __restrict__ src, const int* __restrict__ dst,
    const int* __restrict__ etype)
{
    int wid = threadIdx.x >> 5;
    int lane = threadIdx.x & 31;
    int e0 = blockIdx.x * 16 + wid * 2;          // e0 even -> int2 aligned

    int2 ss = *(const int2*)(src + e0);
    int2 dd = *(const int2*)(dst + e0);
    int2 rr = *(const int2*)(etype + e0);

    const float4* k0p = (const float4*)(g_K + ((size_t)rr.x * N_NODES + ss.x) * D);
    const float4* q0p = (const float4*)(g_Q + ((size_t)rr.x * N_NODES + dd.x) * D);
    const float4* k1p = (const float4*)(g_K + ((size_t)rr.y * N_NODES + ss.y) * D);
    const float4* q1p = (const float4*)(g_Q + ((size_t)rr.y * N_NODES + dd.y) * D);
    float4 k0 = k0p[lane];
    float4 q0 = q0p[lane];
    float4 k1 = k1p[lane];
    float4 q1 = q1p[lane];

    float p0 = k0.x * q0.x + k0.y * q0.y + k0.z * q0.z + k0.w * q0.w;
    float p1 = k1.x * q1.x + k1.y * q1.y + k1.z * q1.z + k1.w * q1.w;
    p0 += __shfl_xor_sync(0xffffffff, p0, 1);
    p1 += __shfl_xor_sync(0xffffffff, p1, 1);
    p0 += __shfl_xor_sync(0xffffffff, p0, 2);
    p1 += __shfl_xor_sync(0xffffffff, p1, 2);
    p0 += __shfl_xor_sync(0xffffffff, p0, 4);
    p1 += __shfl_xor_sync(0xffffffff, p1, 4);

    float ex0 = __expf(p0 * 0.1767766952966369f);   // heads at lanes 0,8,16,24
    float ex1 = __expf(p1 * 0.1767766952966369f);

    float a0 = __shfl_sync(0xffffffff, ex0, 0);
    float a1 = __shfl_sync(0xffffffff, ex0, 8);
    float a2 = __shfl_sync(0xffffffff, ex0, 16);
    float a3 = __shfl_sync(0xffffffff, ex0, 24);
    float b0 = __shfl_sync(0xffffffff, ex1, 0);
    float b1 = __shfl_sync(0xffffffff, ex1, 8);
    float b2 = __shfl_sync(0xffffffff, ex1, 16);
    float b3 = __shfl_sync(0xffffffff, ex1, 24);

    if (lane == 0) {
        int pos = atomicAdd(&g_cursor[dd.x], 1);
        if (pos < MAXDEG) {
            int slot = (dd.x << 7) + pos;
            g_e_idx[slot] = rr.x * N_NODES + ss.x;
            g_e_score[slot] = make_float4(a0, a1, a2, a3);
        }
    } else if (lane == 1) {
        int pos = atomicAdd(&g_cursor[dd.y], 1);
        if (pos < MAXDEG) {
            int slot = (dd.y << 7) + pos;
            g_e_idx[slot] = rr.y * N_NODES + ss.y;
            g_e_score[slot] = make_float4(b0, b1, b2, b3);
        }
    }
}

// Per-destination-node softmax + weighted aggregation. Block (128 thr) per node.
// (R9/R11 measured-best form.)
__global__ void __launch_bounds__(128) agg_kernel()
{
    int n = blockIdx.x;
    int tid = threadIdx.x;
    int deg = min(g_cursor[n], MAXDEG);
    int base = n << 7;

    __shared__ float s_den[R_T * H_H];
    __shared__ float s_inv[R_T * H_H];
    __shared__ int    s_i[32];
    __shared__ float4 s_a[32];

    if (tid < R_T * H_H) s_den[tid] = 0.f;
    __syncthreads();
    if (tid == 0) g_cursor[n] = 0;   // reset for next replay (deg already read)

    for (int j = tid; j < deg; j += 128) {
        int r = g_e_idx[base + j] >> 14;        // N = 2^14
        float4 sc = g_e_score[base + j];
        atomicAdd(&s_den[r * 4 + 0], sc.x);
        atomicAdd(&s_den[r * 4 + 1], sc.y);
        atomicAdd(&s_den[r * 4 + 2], sc.z);
        atomicAdd(&s_den[r * 4 + 3], sc.w);
    }
    __syncthreads();
    if (tid < R_T * H_H) s_inv[tid] = 1.0f / s_den[tid];
    __syncthreads();

    float a0 = 0.f, a1 = 0.f, a2 = 0.f, a3 = 0.f;
    for (int j0 = 0; j0 < deg; j0 += 32) {
        int m = min(32, deg - j0);
        if (tid < m) {
            int idx = g_e_idx[base + j0 + tid];
            int r = idx >> 14;
            float4 sc = g_e_score[base + j0 + tid];
            float4 a;
            a.x = sc.x * s_inv[r * 4 + 0];
            a.y = sc.y * s_inv[r * 4 + 1];
            a.z = sc.z * s_inv[r * 4 + 2];
            a.w = sc.w * s_inv[r * 4 + 3];
            s_a[tid] = a;
            s_i[tid] = idx;
        }
        __syncthreads();
        for (int jj = 0; jj < m; jj++) {
            int vrow = s_i[jj];
            float4 a = s_a[jj];
            float v = g_V[(size_t)vrow * D + tid];
            a0 += a.x * v; a1 += a.y * v; a2 += a.z * v; a3 += a.w * v;
        }
        __syncthreads();
    }

    float* o = g_agg + (size_t)n * 512;
    o[tid]       = a0;
    o[128 + tid] = a1;
    o[256 + tid] = a2;
    o[384 + tid] = a3;
}

// Final projection (tensor-core): out[N,128] = g_agg[N,512] @ Wt[512,128] + bt.
__global__ void __launch_bounds__(512) final_gemm_tc(
    const float* __restrict__ Wt, const float* __restrict__ bt,
    float* __restrict__ out)
{
    extern __shared__ float smem[];
    float* h_s = smem;
    float* w_s = smem + 16384;

    int nodeBase = blockIdx.x * 128;
    int tid = threadIdx.x;
    int lane = tid & 31, wid = tid >> 5;
    int gid = lane >> 2, tig = lane & 3;
    int wrow = wid & 7, wcol = wid >> 3;
    int cbase = wcol * 64;
    int nA = wrow * 16 + gid;
    int xrA = gid << 2;

    const uint32_t* hsu = (const uint32_t*)h_s;
    const uint32_t* wsu = (const uint32_t*)w_s;

    float acc[8][4];
    #pragma unroll
    for (int nt = 0; nt < 8; nt++) {
        float2 bv2 = *(const float2*)(bt + cbase + nt * 8 + 2 * tig);
        acc[nt][0] = bv2.x; acc[nt][1] = bv2.y;
        acc[nt][2] = bv2.x; acc[nt][3] = bv2.y;
    }

    #pragma unroll 1
    for (int kb = 0; kb < 4; kb++) {
        __syncthreads();
        stage_A_rows(h_s, (const float4*)g_agg, 128, nodeBase, kb * 32, tid, 128);
        stage_B(w_s, (const float4*)Wt, kb * 128, tid);
        __syncthreads();
        mma_tile(hsu, wsu, nA, xrA, cbase, gid, tig, acc);
    }

    int row0 = nodeBase + wrow * 16 + gid;
    #pragma unroll
    for (int nt = 0; nt < 8; nt++) {
        int col0 = cbase + nt * 8 + 2 * tig;
        *(float2*)(out + (size_t)row0 * D + col0) =
            make_float2(acc[nt][0], acc[nt][1]);
        *(float2*)(out + (size_t)(row0 + 8) * D + col0) =
            make_float2(acc[nt][2], acc[nt][3]);
    }
}

// ---------------- launch ----------------
extern "C" void kernel_launch(void* const* d_in, const int* in_sizes, int n_in,
                              void* d_out, int out_size)
{
    const float* h  = (const float*)d_in[0];
    const float* Wk = (const float*)d_in[1];
    const float* bk = (const float*)d_in[2];
    const float* Wq = (const float*)d_in[3];
    const float* bq = (const float*)d_in[4];
    const float* Wv = (const float*)d_in[5];
    const float* bv = (const float*)d_in[6];
    const float* Wt = (const float*)d_in[7];
    const float* bt = (const float*)d_in[8];
    const int* src   = (const int*)d_in[9];
    const int* dst   = (const int*)d_in[10];
    const int* etype = (const int*)d_in[11];
    float* out = (float*)d_out;

    const int QKV_SMEM = (256 * 128 + 128 * 128) * 4;   // 192 KB dynamic
    const int FIN_SMEM = 2 * 128 * 128 * 4;             // 128 KB dynamic
    cudaFuncSetAttribute(qkv_gemm_tc,
                         cudaFuncAttributeMaxDynamicSharedMemorySize, QKV_SMEM);
    cudaFuncSetAttribute(final_gemm_tc,
                         cudaFuncAttributeMaxDynamicSharedMemorySize, FIN_SMEM);

    dummy_kernel<<<1, 32>>>();                                    // 1
    dummy_kernel<<<1, 32>>>();                                    // 2
    dummy_kernel<<<1, 32>>>();                                    // 3
    qkv_gemm_tc<<<dim3(N_NODES / 256, R_T), 512, QKV_SMEM>>>(h, Wk, bk, Wq, bq, Wv, bv); // 4 (profiled)
    score_kernel<<<E_EDGES / 16, 256>>>(src, dst, etype);         // 5
    agg_kernel<<<N_NODES, 128>>>();                               // 6
    final_gemm_tc<<<N_NODES / 128, 512, FIN_SMEM>>>(Wt, bt, out); // 7
}

// round 15
// speedup vs baseline: 1.0621x; 1.0621x over previous
#include <cuda_runtime.h>
#include <cuda_bf16.h>
#include <cstdint>

#define N_NODES 16384
#define D       128
#define R_T     5
#define H_H     4
#define E_EDGES 262144
#define MAXDEG  128   // Poisson(16) tail: P(deg>=128) ~ 1e-60

typedef unsigned long long u64;

// ---------------- device scratch (static globals; no allocation) ----------------
__device__ float g_K[R_T * N_NODES * D];      // 41.9 MB
__device__ float g_Q[R_T * N_NODES * D];      // 41.9 MB
__device__ float g_V[R_T * N_NODES * D];      // 41.9 MB
__device__ float g_agg[N_NODES * 512];        // 33.5MB [N][H*D]
__device__ int   g_cursor[N_NODES];           // zero-init; agg resets each replay
__device__ int   g_e_idx[N_NODES * MAXDEG];   // padded CSR: r*N + src
__device__ float4 g_e_score[N_NODES * MAXDEG];// padded CSR: exp(score) per head

// ---------------- helpers ----------------
__device__ __forceinline__ uint32_t f2tf32(float x) {
    uint32_t r;
    asm("cvt.rna.tf32.f32 %0, %1;" : "=r"(r) : "f"(x));
    return r;
}
__device__ __forceinline__ void mma_tf32(float d[4], const uint32_t a[4],
                                         uint32_t b0, uint32_t b1) {
    asm volatile(
        "mma.sync.aligned.m16n8k8.row.col.f32.tf32.tf32.f32 "
        "{%0,%1,%2,%3}, {%4,%5,%6,%7}, {%8,%9}, {%0,%1,%2,%3};"
        : "+f"(d[0]), "+f"(d[1]), "+f"(d[2]), "+f"(d[3])
        : "r"(a[0]), "r"(a[1]), "r"(a[2]), "r"(a[3]), "r"(b0), "r"(b1));
}

// ---- shared tc-GEMM fragment machinery (swizzles verified R7/R8) ----
// Stage nrows x 128 fp32 (row-major) into swizzled tf32 smem tile. 256-thr.
__device__ __forceinline__ void stage_A_rows(
    float* h_s, const float4* __restrict__ src4, int rowStride4, int rowBase,
    int colq0, int tid, int nrows)
{
    for (int idx = tid; idx < nrows * 32; idx += 256) {
        int n  = idx >> 5;
        int kq = idx & 31;
        float4 v = src4[(size_t)(rowBase + n) * rowStride4 + colq0 + kq];
        uint4 t;
        t.x = f2tf32(v.x); t.y = f2tf32(v.y);
        t.z = f2tf32(v.z); t.w = f2tf32(v.w);
        *(uint4*)(h_s + n * 128 + ((kq * 4) ^ ((n & 7) << 2))) = t;
    }
}

__device__ __forceinline__ void stage_B(
    float* w_s, const float4* __restrict__ W4, int kBase, int tid)
{
    for (int idx = tid; idx < 4096; idx += 256) {
        int k  = idx >> 5;
        int cq = idx & 31;
        float4 v = W4[(size_t)(kBase + k) * 32 + cq];
        uint4 t;
        t.x = f2tf32(v.x); t.y = f2tf32(v.y);
        t.z = f2tf32(v.z); t.w = f2tf32(v.w);
        *(uint4*)(w_s + k * 128 + ((cq * 4) ^ ((k & 3) << 3))) = t;
    }
}

// 16 k8-steps, warp tile 16 nodes x 64 cols.
__device__ __forceinline__ void mma_tile(
    const uint32_t* __restrict__ hsu, const uint32_t* __restrict__ wsu,
    int nA, int xrA, int cbase, int gid, int tig, float acc[8][4])
{
    #pragma unroll 4
    for (int ks = 0; ks < 16; ks++) {
        int k0 = ks * 8 + tig;
        int ka  = k0 ^ xrA;
        int ka4 = (k0 + 4) ^ xrA;
        uint32_t a[4];
        a[0] = hsu[(nA    ) * 128 + ka ];
        a[1] = hsu[(nA + 8) * 128 + ka ];
        a[2] = hsu[(nA    ) * 128 + ka4];
        a[3] = hsu[(nA + 8) * 128 + ka4];
        #pragma unroll
        for (int nt = 0; nt < 8; nt++) {
            int cs = (cbase + nt * 8 + gid) ^ (tig << 3);
            uint32_t b0 = wsu[ k0      * 128 + cs];
            uint32_t b1 = wsu[(k0 + 4) * 128 + cs];
            mma_tf32(acc[nt], a, b0, b1);
        }
    }
}

__global__ void dummy_kernel() {}

// Tensor-core QKV: grid (N/64, R), 256 threads, 96 KB dyn smem -> 2 CTAs/SM.
// Block tile 64 nodes x 128 cols; warp tile 16 nodes x 64 cols (8 warps:
// 4 node-rows x 2 col-groups). Cross-CTA overlap hides stage/sync phases.
__global__ void __launch_bounds__(256, 2) qkv_gemm_tc(
    const float* __restrict__ h,
    const float* __restrict__ Wk, const float* __restrict__ bk,
    const float* __restrict__ Wq, const float* __restrict__ bq,
    const float* __restrict__ Wv, const float* __restrict__ bv)
{
    extern __shared__ float smem[];
    float* h_s = smem;            // 64 x 128 tf32 (32 KB)
    float* w_s = smem + 8192;     // 128 x 128 tf32 (64 KB)

    int r = blockIdx.y;
    int nodeBase = blockIdx.x * 64;
    int tid = threadIdx.x;

    stage_A_rows(h_s, (const float4*)h, 32, nodeBase, 0, tid, 64);

    int lane = tid & 31, wid = tid >> 5;
    int gid = lane >> 2, tig = lane & 3;
    int wrow = wid & 3, wcol = wid >> 2;
    int cbase = wcol * 64;
    int nA = wrow * 16 + gid;
    int xrA = gid << 2;

    const uint32_t* hsu = (const uint32_t*)h_s;
    const uint32_t* wsu = (const uint32_t*)w_s;

    #pragma unroll 1
    for (int which = 0; which < 3; which++) {
        const float* W; const float* b; float* out;
        if (which == 0)      { W = Wk; b = bk; out = g_K; }
        else if (which == 1) { W = Wq; b = bq; out = g_Q; }
        else                 { W = Wv; b = bv; out = g_V; }
        W += r * D * D;
        b += r * D;
        out += (size_t)r * N_NODES * D;

        __syncthreads();
        stage_B(w_s, (const float4*)W, 0, tid);
        __syncthreads();

        float acc[8][4];
        #pragma unroll
        for (int nt = 0; nt < 8; nt++) {
            float2 bv2 = *(const float2*)(b + cbase + nt * 8 + 2 * tig);
            acc[nt][0] = bv2.x; acc[nt][1] = bv2.y;
            acc[nt][2] = bv2.x; acc[nt][3] = bv2.y;
        }

        mma_tile(hsu, wsu, nA, xrA, cbase, gid, tig, acc);

        int row0 = nodeBase + wrow * 16 + gid;
        #pragma unroll
        for (int nt = 0; nt < 8; nt++) {
            int col0 = cbase + nt * 8 + 2 * tig;
            *(float2*)(out + (size_t)row0 * D + col0) =
                make_float2(acc[nt][0], acc[nt][1]);
            *(float2*)(out + (size_t)(row0 + 8) * D + col0) =
                make_float2(acc[nt][2], acc[nt][3]);
        }
    }
}

// Per-edge attention scores: 2 edges per warp, MLP-4 gathers, direct CSR write.
__global__ void __launch_bounds__(256) score_kernel(
    const int* __restrict__ src, const int* __restrict__ dst,
    const int* __restrict__ etype)
{
    int wid = threadIdx.x >> 5;
    int lane = threadIdx.x & 31;
    int e0 = blockIdx.x * 16 + wid * 2;          // e0 even -> int2 aligned

    int2 ss = *(const int2*)(src + e0);
    int2 dd = *(const int2*)(dst + e0);
    int2 rr = *(const int2*)(etype + e0);

    const float4* k0p = (const float4*)(g_K + ((size_t)rr.x * N_NODES + ss.x) * D);
    const float4* q0p = (const float4*)(g_Q + ((size_t)rr.x * N_NODES + dd.x) * D);
    const float4* k1p = (const float4*)(g_K + ((size_t)rr.y * N_NODES + ss.y) * D);
    const float4* q1p = (const float4*)(g_Q + ((size_t)rr.y * N_NODES + dd.y) * D);
    float4 k0 = k0p[lane];
    float4 q0 = q0p[lane];
    float4 k1 = k1p[lane];
    float4 q1 = q1p[lane];

    float p0 = k0.x * q0.x + k0.y * q0.y + k0.z * q0.z + k0.w * q0.w;
    float p1 = k1.x * q1.x + k1.y * q1.y + k1.z * q1.z + k1.w * q1.w;
    p0 += __shfl_xor_sync(0xffffffff, p0, 1);
    p1 += __shfl_xor_sync(0xffffffff, p1, 1);
    p0 += __shfl_xor_sync(0xffffffff, p0, 2);
    p1 += __shfl_xor_sync(0xffffffff, p1, 2);
    p0 += __shfl_xor_sync(0xffffffff, p0, 4);
    p1 += __shfl_xor_sync(0xffffffff, p1, 4);

    float ex0 = __expf(p0 * 0.1767766952966369f);   // heads at lanes 0,8,16,24
    float ex1 = __expf(p1 * 0.1767766952966369f);

    float a0 = __shfl_sync(0xffffffff, ex0, 0);
    float a1 = __shfl_sync(0xffffffff, ex0, 8);
    float a2 = __shfl_sync(0xffffffff, ex0, 16);
    float a3 = __shfl_sync(0xffffffff, ex0, 24);
    float b0 = __shfl_sync(0xffffffff, ex1, 0);
    float b1 = __shfl_sync(0xffffffff, ex1, 8);
    float b2 = __shfl_sync(0xffffffff, ex1, 16);
    float b3 = __shfl_sync(0xffffffff, ex1, 24);

    if (lane == 0) {
        int pos = atomicAdd(&g_cursor[dd.x], 1);
        if (pos < MAXDEG) {
            int slot = (dd.x << 7) + pos;
            g_e_idx[slot] = rr.x * N_NODES + ss.x;
            g_e_score[slot] = make_float4(a0, a1, a2, a3);
        }
    } else if (lane == 1) {
        int pos = atomicAdd(&g_cursor[dd.y], 1);
        if (pos < MAXDEG) {
            int slot = (dd.y << 7) + pos;
            g_e_idx[slot] = rr.y * N_NODES + ss.y;
            g_e_score[slot] = make_float4(b0, b1, b2, b3);
        }
    }
}

// Per-destination-node softmax + weighted aggregation. Block (128 thr) per node.
// (R9/R11 measured-best form.)
__global__ void __launch_bounds__(128) agg_kernel()
{
    int n = blockIdx.x;
    int tid = threadIdx.x;
    int deg = min(g_cursor[n], MAXDEG);
    int base = n << 7;

    __shared__ float s_den[R_T * H_H];
    __shared__ float s_inv[R_T * H_H];
    __shared__ int    s_i[32];
    __shared__ float4 s_a[32];

    if (tid < R_T * H_H) s_den[tid] = 0.f;
    __syncthreads();
    if (tid == 0) g_cursor[n] = 0;   // reset for next replay (deg already read)

    for (int j = tid; j < deg; j += 128) {
        int r = g_e_idx[base + j] >> 14;        // N = 2^14
        float4 sc = g_e_score[base + j];
        atomicAdd(&s_den[r * 4 + 0], sc.x);
        atomicAdd(&s_den[r * 4 + 1], sc.y);
        atomicAdd(&s_den[r * 4 + 2], sc.z);
        atomicAdd(&s_den[r * 4 + 3], sc.w);
    }
    __syncthreads();
    if (tid < R_T * H_H) s_inv[tid] = 1.0f / s_den[tid];
    __syncthreads();

    float a0 = 0.f, a1 = 0.f, a2 = 0.f, a3 = 0.f;
    for (int j0 = 0; j0 < deg; j0 += 32) {
        int m = min(32, deg - j0);
        if (tid < m) {
            int idx = g_e_idx[base + j0 + tid];
            int r = idx >> 14;
            float4 sc = g_e_score[base + j0 + tid];
            float4 a;
            a.x = sc.x * s_inv[r * 4 + 0];
            a.y = sc.y * s_inv[r * 4 + 1];
            a.z = sc.z * s_inv[r * 4 + 2];
            a.w = sc.w * s_inv[r * 4 + 3];
            s_a[tid] = a;
            s_i[tid] = idx;
        }
        __syncthreads();
        for (int jj = 0; jj < m; jj++) {
            int vrow = s_i[jj];
            float4 a = s_a[jj];
            float v = g_V[(size_t)vrow * D + tid];
            a0 += a.x * v; a1 += a.y * v; a2 += a.z * v; a3 += a.w * v;
        }
        __syncthreads();
    }

    float* o = g_agg + (size_t)n * 512;
    o[tid]       = a0;
    o[128 + tid] = a1;
    o[256 + tid] = a2;
    o[384 + tid] = a3;
}

// Final projection (tensor-core): out[N,128] = g_agg[N,512] @ Wt[512,128] + bt.
// Grid N/64, 256 threads, 96 KB -> 2 CTAs/SM; k staged in four 128-chunks.
__global__ void __launch_bounds__(256, 2) final_gemm_tc(
    const float* __restrict__ Wt, const float* __restrict__ bt,
    float* __restrict__ out)
{
    extern __shared__ float smem[];
    float* h_s = smem;            // 64 x 128 tf32 (32 KB)
    float* w_s = smem + 8192;     // 128 x 128 tf32 (64 KB)

    int nodeBase = blockIdx.x * 64;
    int tid = threadIdx.x;
    int lane = tid & 31, wid = tid >> 5;
    int gid = lane >> 2, tig = lane & 3;
    int wrow = wid & 3, wcol = wid >> 2;
    int cbase = wcol * 64;
    int nA = wrow * 16 + gid;
    int xrA = gid << 2;

    const uint32_t* hsu = (const uint32_t*)h_s;
    const uint32_t* wsu = (const uint32_t*)w_s;

    float acc[8][4];
    #pragma unroll
    for (int nt = 0; nt < 8; nt++) {
        float2 bv2 = *(const float2*)(bt + cbase + nt * 8 + 2 * tig);
        acc[nt][0] = bv2.x; acc[nt][1] = bv2.y;
        acc[nt][2] = bv2.x; acc[nt][3] = bv2.y;
    }

    #pragma unroll 1
    for (int kb = 0; kb < 4; kb++) {
        __syncthreads();
        stage_A_rows(h_s, (const float4*)g_agg, 128, nodeBase, kb * 32, tid, 64);
        stage_B(w_s, (const float4*)Wt, kb * 128, tid);
        __syncthreads();
        mma_tile(hsu, wsu, nA, xrA, cbase, gid, tig, acc);
    }

    int row0 = nodeBase + wrow * 16 + gid;
    #pragma unroll
    for (int nt = 0; nt < 8; nt++) {
        int col0 = cbase + nt * 8 + 2 * tig;
        *(float2*)(out + (size_t)row0 * D + col0) =
            make_float2(acc[nt][0], acc[nt][1]);
        *(float2*)(out + (size_t)(row0 + 8) * D + col0) =
            make_float2(acc[nt][2], acc[nt][3]);
    }
}

// ---------------- launch ----------------
extern "C" void kernel_launch(void* const* d_in, const int* in_sizes, int n_in,
                              void* d_out, int out_size)
{
    const float* h  = (const float*)d_in[0];
    const float* Wk = (const float*)d_in[1];
    const float* bk = (const float*)d_in[2];
    const float* Wq = (const float*)d_in[3];
    const float* bq = (const float*)d_in[4];
    const float* Wv = (const float*)d_in[5];
    const float* bv = (const float*)d_in[6];
    const float* Wt = (const float*)d_in[7];
    const float* bt = (const float*)d_in[8];
    const int* src   = (const int*)d_in[9];
    const int* dst   = (const int*)d_in[10];
    const int* etype = (const int*)d_in[11];
    float* out = (float*)d_out;

    const int TC_SMEM = (64 * 128 + 128 * 128) * 4;   // 96 KB dynamic
    cudaFuncSetAttribute(qkv_gemm_tc,
                         cudaFuncAttributeMaxDynamicSharedMemorySize, TC_SMEM);
    cudaFuncSetAttribute(final_gemm_tc,
                         cudaFuncAttributeMaxDynamicSharedMemorySize, TC_SMEM);

    dummy_kernel<<<1, 32>>>();                                    // 1
    dummy_kernel<<<1, 32>>>();                                    // 2
    dummy_kernel<<<1, 32>>>();                                    // 3
    qkv_gemm_tc<<<dim3(N_NODES / 64, R_T), 256, TC_SMEM>>>(h, Wk, bk, Wq, bq, Wv, bv); // 4 (profiled)
    score_kernel<<<E_EDGES / 16, 256>>>(src, dst, etype);         // 5
    agg_kernel<<<N_NODES, 128>>>();                               // 6
    final_gemm_tc<<<N_NODES / 64, 256, TC_SMEM>>>(Wt, bt, out);   // 7
}

// round 16
// speedup vs baseline: 1.1008x; 1.0364x over previous
#include <cuda_runtime.h>
#include <cuda_bf16.h>
#include <cstdint>

#define N_NODES 16384
#define D       128
#define R_T     5
#define H_H     4
#define E_EDGES 262144
#define MAXDEG  128   // Poisson(16) tail: P(deg>=128) ~ 1e-60

typedef unsigned long long u64;

// ---------------- device scratch (static globals; no allocation) ----------------
__device__ float g_K[R_T * N_NODES * D];      // 41.9 MB
__device__ float g_Q[R_T * N_NODES * D];      // 41.9 MB
__device__ float g_V[R_T * N_NODES * D];      // 41.9 MB
__device__ float g_agg[N_NODES * 512];        // 33.5MB [N][H*D]
__device__ int   g_cursor[N_NODES];           // zero-init; agg resets each replay
__device__ int   g_e_idx[N_NODES * MAXDEG];   // padded CSR: r*N + src
__device__ float4 g_e_score[N_NODES * MAXDEG];// padded CSR: exp(score) per head

// ---------------- helpers ----------------
__device__ __forceinline__ uint32_t f2tf32(float x) {
    uint32_t r;
    asm("cvt.rna.tf32.f32 %0, %1;" : "=r"(r) : "f"(x));
    return r;
}
__device__ __forceinline__ void mma_tf32(float d[4], const uint32_t a[4],
                                         uint32_t b0, uint32_t b1) {
    asm volatile(
        "mma.sync.aligned.m16n8k8.row.col.f32.tf32.tf32.f32 "
        "{%0,%1,%2,%3}, {%4,%5,%6,%7}, {%8,%9}, {%0,%1,%2,%3};"
        : "+f"(d[0]), "+f"(d[1]), "+f"(d[2]), "+f"(d[3])
        : "r"(a[0]), "r"(a[1]), "r"(a[2]), "r"(a[3]), "r"(b0), "r"(b1));
}

// ---- shared tc-GEMM fragment machinery (swizzles verified R7/R8) ----
// Stage nrows x 128 fp32 (row-major) into swizzled tf32 smem tile. 256-thr.
__device__ __forceinline__ void stage_A_rows(
    float* h_s, const float4* __restrict__ src4, int rowStride4, int rowBase,
    int colq0, int tid, int nrows)
{
    for (int idx = tid; idx < nrows * 32; idx += 256) {
        int n  = idx >> 5;
        int kq = idx & 31;
        float4 v = src4[(size_t)(rowBase + n) * rowStride4 + colq0 + kq];
        uint4 t;
        t.x = f2tf32(v.x); t.y = f2tf32(v.y);
        t.z = f2tf32(v.z); t.w = f2tf32(v.w);
        *(uint4*)(h_s + n * 128 + ((kq * 4) ^ ((n & 7) << 2))) = t;
    }
}

// Stage nk k-rows of W (k-major, 128 cols) into swizzled tf32 w_s.
__device__ __forceinline__ void stage_B_rows(
    float* w_s, const float4* __restrict__ W4, int kBase, int tid, int nk)
{
    for (int idx = tid; idx < nk * 32; idx += 256) {
        int k  = idx >> 5;
        int cq = idx & 31;
        float4 v = W4[(size_t)(kBase + k) * 32 + cq];
        uint4 t;
        t.x = f2tf32(v.x); t.y = f2tf32(v.y);
        t.z = f2tf32(v.z); t.w = f2tf32(v.w);
        *(uint4*)(w_s + k * 128 + ((cq * 4) ^ ((k & 3) << 3))) = t;
    }
}

// 16 k8-steps, warp tile 16 nodes x 64 cols (used by final_gemm_tc).
__device__ __forceinline__ void mma_tile(
    const uint32_t* __restrict__ hsu, const uint32_t* __restrict__ wsu,
    int nA, int xrA, int cbase, int gid, int tig, float acc[8][4])
{
    #pragma unroll 4
    for (int ks = 0; ks < 16; ks++) {
        int k0 = ks * 8 + tig;
        int ka  = k0 ^ xrA;
        int ka4 = (k0 + 4) ^ xrA;
        uint32_t a[4];
        a[0] = hsu[(nA    ) * 128 + ka ];
        a[1] = hsu[(nA + 8) * 128 + ka ];
        a[2] = hsu[(nA    ) * 128 + ka4];
        a[3] = hsu[(nA + 8) * 128 + ka4];
        #pragma unroll
        for (int nt = 0; nt < 8; nt++) {
            int cs = (cbase + nt * 8 + gid) ^ (tig << 3);
            uint32_t b0 = wsu[ k0      * 128 + cs];
            uint32_t b1 = wsu[(k0 + 4) * 128 + cs];
            mma_tf32(acc[nt], a, b0, b1);
        }
    }
}

__global__ void dummy_kernel() {}

// Tensor-core QKV: grid (N/128, R), 256 threads, 96 KB -> 2 CTAs/SM.
// Block tile 128 nodes x 128 cols; warp tile 32 nodes x 64 cols (wide-M:
// 1.5 LDS/mma). W staged in two 64-k halves (w_s only 32 KB).
__global__ void __launch_bounds__(256, 2) qkv_gemm_tc(
    const float* __restrict__ h,
    const float* __restrict__ Wk, const float* __restrict__ bk,
    const float* __restrict__ Wq, const float* __restrict__ bq,
    const float* __restrict__ Wv, const float* __restrict__ bv)
{
    extern __shared__ float smem[];
    float* h_s = smem;            // 128 x 128 tf32 (64 KB)
    float* w_s = smem + 16384;    // 64 x 128 tf32 (32 KB)

    int r = blockIdx.y;
    int nodeBase = blockIdx.x * 128;
    int tid = threadIdx.x;

    stage_A_rows(h_s, (const float4*)h, 32, nodeBase, 0, tid, 128);

    int lane = tid & 31, wid = tid >> 5;
    int gid = lane >> 2, tig = lane & 3;
    int wrow = wid & 3, wcol = wid >> 2;
    int cbase = wcol * 64;
    int nA = wrow * 32 + gid;
    int xrA = gid << 2;

    const uint32_t* hsu = (const uint32_t*)h_s;
    const uint32_t* wsu = (const uint32_t*)w_s;

    #pragma unroll 1
    for (int which = 0; which < 3; which++) {
        const float* W; const float* b; float* out;
        if (which == 0)      { W = Wk; b = bk; out = g_K; }
        else if (which == 1) { W = Wq; b = bq; out = g_Q; }
        else                 { W = Wv; b = bv; out = g_V; }
        W += r * D * D;
        b += r * D;
        out += (size_t)r * N_NODES * D;

        float acc[2][8][4];
        #pragma unroll
        for (int nt = 0; nt < 8; nt++) {
            float2 bv2 = *(const float2*)(b + cbase + nt * 8 + 2 * tig);
            #pragma unroll
            for (int mt = 0; mt < 2; mt++) {
                acc[mt][nt][0] = bv2.x; acc[mt][nt][1] = bv2.y;
                acc[mt][nt][2] = bv2.x; acc[mt][nt][3] = bv2.y;
            }
        }

        #pragma unroll 1
        for (int kc = 0; kc < 2; kc++) {
            __syncthreads();   // w_s free of prior readers
            stage_B_rows(w_s, (const float4*)W, kc * 64, tid, 64);
            __syncthreads();

            #pragma unroll 4
            for (int ks = 0; ks < 8; ks++) {
                int k0l = ks * 8 + tig;            // local k for w_s
                int k0g = kc * 64 + k0l;           // global k for h_s
                int ka  = k0g ^ xrA;
                int ka4 = (k0g + 4) ^ xrA;
                uint32_t a0[4], a1[4];
                a0[0] = hsu[(nA     ) * 128 + ka ];
                a0[1] = hsu[(nA +  8) * 128 + ka ];
                a0[2] = hsu[(nA     ) * 128 + ka4];
                a0[3] = hsu[(nA +  8) * 128 + ka4];
                a1[0] = hsu[(nA + 16) * 128 + ka ];
                a1[1] = hsu[(nA + 24) * 128 + ka ];
                a1[2] = hsu[(nA + 16) * 128 + ka4];
                a1[3] = hsu[(nA + 24) * 128 + ka4];
                #pragma unroll
                for (int nt = 0; nt < 8; nt++) {
                    int cs = (cbase + nt * 8 + gid) ^ (tig << 3);
                    uint32_t b0 = wsu[ k0l      * 128 + cs];
                    uint32_t b1 = wsu[(k0l + 4) * 128 + cs];
                    mma_tf32(acc[0][nt], a0, b0, b1);
                    mma_tf32(acc[1][nt], a1, b0, b1);
                }
            }
        }

        #pragma unroll
        for (int mt = 0; mt < 2; mt++) {
            int row0 = nodeBase + wrow * 32 + mt * 16 + gid;
            #pragma unroll
            for (int nt = 0; nt < 8; nt++) {
                int col0 = cbase + nt * 8 + 2 * tig;
                *(float2*)(out + (size_t)row0 * D + col0) =
                    make_float2(acc[mt][nt][0], acc[mt][nt][1]);
                *(float2*)(out + (size_t)(row0 + 8) * D + col0) =
                    make_float2(acc[mt][nt][2], acc[mt][nt][3]);
            }
        }
    }
}

// Per-edge attention scores: 2 edges per warp, MLP-4 gathers, direct CSR write.
__global__ void __launch_bounds__(256) score_kernel(
    const int* __restrict__ src, const int* __restrict__ dst,
    const int* __restrict__ etype)
{
    int wid = threadIdx.x >> 5;
    int lane = threadIdx.x & 31;
    int e0 = blockIdx.x * 16 + wid * 2;          // e0 even -> int2 aligned

    int2 ss = *(const int2*)(src + e0);
    int2 dd = *(const int2*)(dst + e0);
    int2 rr = *(const int2*)(etype + e0);

    const float4* k0p = (const float4*)(g_K + ((size_t)rr.x * N_NODES + ss.x) * D);
    const float4* q0p = (const float4*)(g_Q + ((size_t)rr.x * N_NODES + dd.x) * D);
    const float4* k1p = (const float4*)(g_K + ((size_t)rr.y * N_NODES + ss.y) * D);
    const float4* q1p = (const float4*)(g_Q + ((size_t)rr.y * N_NODES + dd.y) * D);
    float4 k0 = k0p[lane];
    float4 q0 = q0p[lane];
    float4 k1 = k1p[lane];
    float4 q1 = q1p[lane];

    float p0 = k0.x * q0.x + k0.y * q0.y + k0.z * q0.z + k0.w * q0.w;
    float p1 = k1.x * q1.x + k1.y * q1.y + k1.z * q1.z + k1.w * q1.w;
    p0 += __shfl_xor_sync(0xffffffff, p0, 1);
    p1 += __shfl_xor_sync(0xffffffff, p1, 1);
    p0 += __shfl_xor_sync(0xffffffff, p0, 2);
    p1 += __shfl_xor_sync(0xffffffff, p1, 2);
    p0 += __shfl_xor_sync(0xffffffff, p0, 4);
    p1 += __shfl_xor_sync(0xffffffff, p1, 4);

    float ex0 = __expf(p0 * 0.1767766952966369f);   // heads at lanes 0,8,16,24
    float ex1 = __expf(p1 * 0.1767766952966369f);

    float a0 = __shfl_sync(0xffffffff, ex0, 0);
    float a1 = __shfl_sync(0xffffffff, ex0, 8);
    float a2 = __shfl_sync(0xffffffff, ex0, 16);
    float a3 = __shfl_sync(0xffffffff, ex0, 24);
    float b0 = __shfl_sync(0xffffffff, ex1, 0);
    float b1 = __shfl_sync(0xffffffff, ex1, 8);
    float b2 = __shfl_sync(0xffffffff, ex1, 16);
    float b3 = __shfl_sync(0xffffffff, ex1, 24);

    if (lane == 0) {
        int pos = atomicAdd(&g_cursor[dd.x], 1);
        if (pos < MAXDEG) {
            int slot = (dd.x << 7) + pos;
            g_e_idx[slot] = rr.x * N_NODES + ss.x;
            g_e_score[slot] = make_float4(a0, a1, a2, a3);
        }
    } else if (lane == 1) {
        int pos = atomicAdd(&g_cursor[dd.y], 1);
        if (pos < MAXDEG) {
            int slot = (dd.y << 7) + pos;
            g_e_idx[slot] = rr.y * N_NODES + ss.y;
            g_e_score[slot] = make_float4(b0, b1, b2, b3);
        }
    }
}

// Per-destination-node softmax + weighted aggregation. Block (128 thr) per node.
// (R9/R11 measured-best form.)
__global__ void __launch_bounds__(128) agg_kernel()
{
    int n = blockIdx.x;
    int tid = threadIdx.x;
    int deg = min(g_cursor[n], MAXDEG);
    int base = n << 7;

    __shared__ float s_den[R_T * H_H];
    __shared__ float s_inv[R_T * H_H];
    __shared__ int    s_i[32];
    __shared__ float4 s_a[32];

    if (tid < R_T * H_H) s_den[tid] = 0.f;
    __syncthreads();
    if (tid == 0) g_cursor[n] = 0;   // reset for next replay (deg already read)

    for (int j = tid; j < deg; j += 128) {
        int r = g_e_idx[base + j] >> 14;        // N = 2^14
        float4 sc = g_e_score[base + j];
        atomicAdd(&s_den[r * 4 + 0], sc.x);
        atomicAdd(&s_den[r * 4 + 1], sc.y);
        atomicAdd(&s_den[r * 4 + 2], sc.z);
        atomicAdd(&s_den[r * 4 + 3], sc.w);
    }
    __syncthreads();
    if (tid < R_T * H_H) s_inv[tid] = 1.0f / s_den[tid];
    __syncthreads();

    float a0 = 0.f, a1 = 0.f, a2 = 0.f, a3 = 0.f;
    for (int j0 = 0; j0 < deg; j0 += 32) {
        int m = min(32, deg - j0);
        if (tid < m) {
            int idx = g_e_idx[base + j0 + tid];
            int r = idx >> 14;
            float4 sc = g_e_score[base + j0 + tid];
            float4 a;
            a.x = sc.x * s_inv[r * 4 + 0];
            a.y = sc.y * s_inv[r * 4 + 1];
            a.z = sc.z * s_inv[r * 4 + 2];
            a.w = sc.w * s_inv[r * 4 + 3];
            s_a[tid] = a;
            s_i[tid] = idx;
        }
        __syncthreads();
        for (int jj = 0; jj < m; jj++) {
            int vrow = s_i[jj];
            float4 a = s_a[jj];
            float v = g_V[(size_t)vrow * D + tid];
            a0 += a.x * v; a1 += a.y * v; a2 += a.z * v; a3 += a.w * v;
        }
        __syncthreads();
    }

    float* o = g_agg + (size_t)n * 512;
    o[tid]       = a0;
    o[128 + tid] = a1;
    o[256 + tid] = a2;
    o[384 + tid] = a3;
}

// Final projection (tensor-core): out[N,128] = g_agg[N,512] @ Wt[512,128] + bt.
// Grid N/64, 256 threads, 96 KB -> 2 CTAs/SM; k staged in four 128-chunks.
__global__ void __launch_bounds__(256, 2) final_gemm_tc(
    const float* __restrict__ Wt, const float* __restrict__ bt,
    float* __restrict__ out)
{
    extern __shared__ float smem[];
    float* h_s = smem;            // 64 x 128 tf32 (32 KB)
    float* w_s = smem + 8192;     // 128 x 128 tf32 (64 KB)

    int nodeBase = blockIdx.x * 64;
    int tid = threadIdx.x;
    int lane = tid & 31, wid = tid >> 5;
    int gid = lane >> 2, tig = lane & 3;
    int wrow = wid & 3, wcol = wid >> 2;
    int cbase = wcol * 64;
    int nA = wrow * 16 + gid;
    int xrA = gid << 2;

    const uint32_t* hsu = (const uint32_t*)h_s;
    const uint32_t* wsu = (const uint32_t*)w_s;

    float acc[8][4];
    #pragma unroll
    for (int nt = 0; nt < 8; nt++) {
        float2 bv2 = *(const float2*)(bt + cbase + nt * 8 + 2 * tig);
        acc[nt][0] = bv2.x; acc[nt][1] = bv2.y;
        acc[nt][2] = bv2.x; acc[nt][3] = bv2.y;
    }

    #pragma unroll 1
    for (int kb = 0; kb < 4; kb++) {
        __syncthreads();
        stage_A_rows(h_s, (const float4*)g_agg, 128, nodeBase, kb * 32, tid, 64);
        stage_B_rows(w_s, (const float4*)Wt, kb * 128, tid, 128);
        __syncthreads();
        mma_tile(hsu, wsu, nA, xrA, cbase, gid, tig, acc);
    }

    int row0 = nodeBase + wrow * 16 + gid;
    #pragma unroll
    for (int nt = 0; nt < 8; nt++) {
        int col0 = cbase + nt * 8 + 2 * tig;
        *(float2*)(out + (size_t)row0 * D + col0) =
            make_float2(acc[nt][0], acc[nt][1]);
        *(float2*)(out + (size_t)(row0 + 8) * D + col0) =
            make_float2(acc[nt][2], acc[nt][3]);
    }
}

// ---------------- launch ----------------
extern "C" void kernel_launch(void* const* d_in, const int* in_sizes, int n_in,
                              void* d_out, int out_size)
{
    const float* h  = (const float*)d_in[0];
    const float* Wk = (const float*)d_in[1];
    const float* bk = (const float*)d_in[2];
    const float* Wq = (const float*)d_in[3];
    const float* bq = (const float*)d_in[4];
    const float* Wv = (const float*)d_in[5];
    const float* bv = (const float*)d_in[6];
    const float* Wt = (const float*)d_in[7];
    const float* bt = (const float*)d_in[8];
    const int* src   = (const int*)d_in[9];
    const int* dst   = (const int*)d_in[10];
    const int* etype = (const int*)d_in[11];
    float* out = (float*)d_out;

    const int TC_SMEM = (64 * 128 + 128 * 128) * 4;   // 96 KB dynamic
    cudaFuncSetAttribute(qkv_gemm_tc,
                         cudaFuncAttributeMaxDynamicSharedMemorySize, TC_SMEM);
    cudaFuncSetAttribute(final_gemm_tc,
                         cudaFuncAttributeMaxDynamicSharedMemorySize, TC_SMEM);

    dummy_kernel<<<1, 32>>>();                                    // 1
    dummy_kernel<<<1, 32>>>();                                    // 2
    dummy_kernel<<<1, 32>>>();                                    // 3
    qkv_gemm_tc<<<dim3(N_NODES / 128, R_T), 256, TC_SMEM>>>(h, Wk, bk, Wq, bq, Wv, bv); // 4 (profiled)
    score_kernel<<<E_EDGES / 16, 256>>>(src, dst, etype);         // 5
    agg_kernel<<<N_NODES, 128>>>();                               // 6
    final_gemm_tc<<<N_NODES / 64, 256, TC_SMEM>>>(Wt, bt, out);   // 7
}